// round 1
// baseline (speedup 1.0000x reference)
#include <cuda_runtime.h>
#include <math.h>

#define DNODE 64
#define NMAX  100000
#define EMAX  1200000
#define EPSN  1e-15f
#define ACLIP (1.0f - 1e-7f)

// ---------------- scratch (no allocation allowed) ----------------
__device__ float g_h[(size_t)NMAX * DNODE];    // linear-layer output
__device__ float g_buf[(size_t)NMAX * DNODE];  // neigh accumulator / layer output x
__device__ float g_deg[NMAX];                  // degree -> inv_degree (in place)

// ---------------- degree ----------------
__global__ void zero_deg_k(float* deg, int n) {
    int i = blockIdx.x * blockDim.x + threadIdx.x;
    if (i < n) deg[i] = 0.0f;
}

__global__ void count_deg_k(const int* __restrict__ dst, float* __restrict__ deg, int E) {
    int i = blockIdx.x * blockDim.x + threadIdx.x;
    if (i < E) atomicAdd(&deg[dst[i]], 1.0f);
}

__global__ void inv_deg_k(float* deg, int n) {
    int i = blockIdx.x * blockDim.x + threadIdx.x;
    if (i < n) {
        float d = deg[i];
        deg[i] = (d > 0.0f) ? (1.0f / fmaxf(d, 1.0f)) : 0.0f;
    }
}

// ---------------- zero fill (float4) ----------------
__global__ void zero_f4_k(float4* p, int n4) {
    int i = blockIdx.x * blockDim.x + threadIdx.x;
    if (i < n4) p[i] = make_float4(0.f, 0.f, 0.f, 0.f);
}

// ---------------- fused logmap0 + Linear (h = logmap0(x) @ W^T + b) ----------------
// warp per row; 8 rows per 256-thread block. W cached in smem, pad 65 (conflict-free).
__global__ __launch_bounds__(256) void logmap_linear_k(
    const float* __restrict__ x, const float* __restrict__ W,
    const float* __restrict__ b, const float* __restrict__ curv,
    float* __restrict__ out, int n)
{
    __shared__ float Wsh[DNODE][DNODE + 1];  // Wsh[j][k] = W[j*D+k]
    __shared__ float bsh[DNODE];
    __shared__ float tsh[8][DNODE];

    int tid = threadIdx.x;
    for (int i = tid; i < DNODE * DNODE; i += 256)
        Wsh[i >> 6][i & 63] = W[i];
    if (tid < DNODE) bsh[tid] = b[tid];
    __syncthreads();

    int warp = tid >> 5, lane = tid & 31;
    int row  = blockIdx.x * 8 + warp;
    if (row >= n) return;

    float sc = sqrtf(fabsf(curv[0]));

    const float* xr = x + (size_t)row * DNODE;
    float xa = xr[lane], xb = xr[lane + 32];
    float ss = xa * xa + xb * xb;
    #pragma unroll
    for (int o = 16; o; o >>= 1) ss += __shfl_xor_sync(0xffffffffu, ss, o);
    float norm = fmaxf(sqrtf(ss), EPSN);
    float arg  = fminf(sc * norm, ACLIP);
    float fac  = atanhf(arg) / (sc * norm);

    tsh[warp][lane]      = fac * xa;
    tsh[warp][lane + 32] = fac * xb;
    __syncwarp();

    float ha = bsh[lane], hb = bsh[lane + 32];
    #pragma unroll
    for (int k = 0; k < DNODE; k++) {
        float t = tsh[warp][k];
        ha = fmaf(t, Wsh[lane][k],      ha);
        hb = fmaf(t, Wsh[lane + 32][k], hb);
    }
    float* orow = out + (size_t)row * DNODE;
    orow[lane]      = ha;
    orow[lane + 32] = hb;
}

// ---------------- edge scatter: neigh[dst] += h[src], vector red.v4 ----------------
// 16 threads per edge (one float4 chunk each).
__global__ __launch_bounds__(256) void scatter_add_k(
    const float* __restrict__ h, const int* __restrict__ src,
    const int* __restrict__ dst, float* __restrict__ neigh, int E)
{
    long long t = (long long)blockIdx.x * blockDim.x + threadIdx.x;
    int e = (int)(t >> 4);
    if (e >= E) return;
    int ch = (int)(t & 15);
    int s = src[e], d = dst[e];
    const float4 v = *reinterpret_cast<const float4*>(h + (size_t)s * DNODE + ch * 4);
    float* p = neigh + (size_t)d * DNODE + ch * 4;
    asm volatile("red.global.add.v4.f32 [%0], {%1,%2,%3,%4};"
                 :: "l"(p), "f"(v.x), "f"(v.y), "f"(v.z), "f"(v.w)
                 : "memory");
}

// ---------------- expmap0( neigh * inv_deg ) ----------------
// warp per row.
__global__ __launch_bounds__(256) void expmap_scale_k(
    const float* __restrict__ neigh, const float* __restrict__ invd,
    const float* __restrict__ curv, float* __restrict__ out, int n)
{
    int gw = (blockIdx.x * blockDim.x + threadIdx.x) >> 5;
    int lane = threadIdx.x & 31;
    if (gw >= n) return;
    float sc = sqrtf(fabsf(curv[0]));
    float w = invd[gw];
    const float* ur = neigh + (size_t)gw * DNODE;
    float ua = ur[lane] * w, ub = ur[lane + 32] * w;
    float ss = ua * ua + ub * ub;
    #pragma unroll
    for (int o = 16; o; o >>= 1) ss += __shfl_xor_sync(0xffffffffu, ss, o);
    float norm = fmaxf(sqrtf(ss), EPSN);
    float fac  = tanhf(sc * norm) / (sc * norm);
    float* orow = out + (size_t)gw * DNODE;
    orow[lane]      = fac * ua;
    orow[lane + 32] = fac * ub;
}

// ---------------- launch ----------------
extern "C" void kernel_launch(void* const* d_in, const int* in_sizes, int n_in,
                              void* d_out, int out_size)
{
    const int*   src  = (const int*)d_in[0];
    const int*   dst  = (const int*)d_in[1];
    const float* emb  = (const float*)d_in[2];
    const float* W1   = (const float*)d_in[3];
    const float* b1   = (const float*)d_in[4];
    const float* W2   = (const float*)d_in[5];
    const float* b2   = (const float*)d_in[6];
    const float* curv = (const float*)d_in[7];
    float* out = (float*)d_out;

    const int E = in_sizes[0];
    const int N = in_sizes[2] / DNODE;

    float *h, *buf, *deg;
    cudaGetSymbolAddress((void**)&h,   g_h);
    cudaGetSymbolAddress((void**)&buf, g_buf);
    cudaGetSymbolAddress((void**)&deg, g_deg);

    const int TB = 256;
    int nd4 = N * DNODE / 4;

    // degrees -> inverse degrees (in place in g_deg)
    zero_deg_k<<<(N + TB - 1) / TB, TB>>>(deg, N);
    count_deg_k<<<(E + TB - 1) / TB, TB>>>(dst, deg, E);
    inv_deg_k<<<(N + TB - 1) / TB, TB>>>(deg, N);

    int rows_blocks = (N + 7) / 8;
    long long sthreads = (long long)E * 16;
    int sblocks = (int)((sthreads + TB - 1) / TB);

    // ---- layer 1 ----
    logmap_linear_k<<<rows_blocks, TB>>>(emb, W1, b1, curv, h, N);
    zero_f4_k<<<(nd4 + TB - 1) / TB, TB>>>((float4*)buf, nd4);
    scatter_add_k<<<sblocks, TB>>>(h, src, dst, buf, E);
    expmap_scale_k<<<rows_blocks, TB>>>(buf, deg, curv, buf, N);   // x1 in g_buf

    // ---- layer 2 ----
    logmap_linear_k<<<rows_blocks, TB>>>(buf, W2, b2, curv, h, N);
    zero_f4_k<<<(nd4 + TB - 1) / TB, TB>>>((float4*)buf, nd4);
    scatter_add_k<<<sblocks, TB>>>(h, src, dst, buf, E);
    expmap_scale_k<<<rows_blocks, TB>>>(buf, deg, curv, out, N);   // final x -> d_out
}

// round 6
// speedup vs baseline: 2.0690x; 2.0690x over previous
#include <cuda_runtime.h>
#include <math.h>

#define DNODE 64
#define NMAX  100000
#define EMAX  1200000
#define EPSN  1e-15f
#define ACLIP (1.0f - 1e-7f)
#define SCAN_BLK 4096

// ---------------- scratch (no allocation allowed) ----------------
__device__ float g_h[(size_t)NMAX * DNODE];    // linear-layer output
__device__ float g_buf[(size_t)NMAX * DNODE];  // pull accumulator
__device__ int   g_csr[EMAX];                  // src ids grouped by dst
__device__ int   g_rs[NMAX + 1];               // row_start (CSR offsets by dst)
__device__ int   g_deg[NMAX];
__device__ int   g_cur[NMAX];
__device__ int   g_incl[NMAX];
__device__ int   g_part[64];
__device__ float g_inv[NMAX];

// ============ CSR build ============
__global__ void zero_int_k(int* a, int n) {
    int i = blockIdx.x * blockDim.x + threadIdx.x;
    if (i < n) a[i] = 0;
}

__global__ void count_k(const int* __restrict__ dst, int* __restrict__ deg, int E) {
    int i = blockIdx.x * blockDim.x + threadIdx.x;
    if (i < E) atomicAdd(&deg[dst[i]], 1);
}

// per-block inclusive scan (4096 elems/block) + block partial sums
__global__ __launch_bounds__(256) void scan1_k(const int* __restrict__ deg,
                                               int* __restrict__ incl,
                                               int* __restrict__ part, int n) {
    __shared__ int sh[256];
    int tid = threadIdx.x;
    int base = blockIdx.x * SCAN_BLK + tid * 16;
    int v[16];
    int s = 0;
    #pragma unroll
    for (int i = 0; i < 16; i++) {
        int idx = base + i;
        v[i] = (idx < n) ? deg[idx] : 0;
        s += v[i];
    }
    sh[tid] = s;
    __syncthreads();
    for (int off = 1; off < 256; off <<= 1) {
        int t = (tid >= off) ? sh[tid - off] : 0;
        __syncthreads();
        sh[tid] += t;
        __syncthreads();
    }
    int run = sh[tid] - s;  // exclusive prefix of this thread within block
    #pragma unroll
    for (int i = 0; i < 16; i++) {
        run += v[i];
        int idx = base + i;
        if (idx < n) incl[idx] = run;
    }
    if (tid == 255) part[blockIdx.x] = sh[255];
}

__global__ void scan2_k(int* part, int nb) {
    if (threadIdx.x == 0 && blockIdx.x == 0) {
        int run = 0;
        for (int b = 0; b < nb; b++) { int t = part[b]; part[b] = run; run += t; }
    }
}

__global__ void finalize_k(const int* __restrict__ incl, const int* __restrict__ deg,
                           const int* __restrict__ part, int* __restrict__ rs,
                           int* __restrict__ cur, float* __restrict__ inv,
                           int n, int E) {
    int i = blockIdx.x * blockDim.x + threadIdx.x;
    if (i < n) {
        int d = deg[i];
        rs[i] = incl[i] - d + part[i / SCAN_BLK];  // exclusive scan
        cur[i] = 0;
        inv[i] = (d > 0) ? (1.0f / (float)d) : 0.0f;
    }
    if (i == 0) rs[n] = E;
}

__global__ void fill_k(const int* __restrict__ src, const int* __restrict__ dst,
                       const int* __restrict__ rs, int* __restrict__ cur,
                       int* __restrict__ csr, int E) {
    int e = blockIdx.x * blockDim.x + threadIdx.x;
    if (e < E) {
        int d = dst[e];
        int p = atomicAdd(&cur[d], 1);
        csr[rs[d] + p] = src[e];
    }
}

// ============ GEMM: out = (scale(row) * X) @ W^T + b ============
// LOGMAP=1: scale = atanh-factor from row norm. LOGMAP=0: scale = invd[row].
// Block: 64 rows x 64 cols; 256 threads; each thread 4 rows x 4 cols; float4 k-chunks.
#define PITCH 68
template <int LOGMAP>
__global__ __launch_bounds__(256) void gemm_k(
    const float* __restrict__ X, const float* __restrict__ W,
    const float* __restrict__ bias, const float* __restrict__ curv,
    const float* __restrict__ invd, float* __restrict__ out, int n)
{
    __shared__ float Xs[DNODE * PITCH];
    __shared__ float Ws[DNODE * PITCH];
    __shared__ float fac[DNODE];
    __shared__ float bsh[DNODE];

    int tid = threadIdx.x;
    int rowbase = blockIdx.x * DNODE;

    // stage W (4096 floats) and X tile
    for (int i = tid * 4; i < DNODE * DNODE; i += 1024) {
        int r = i >> 6, c = i & 63;
        float4 w = *(const float4*)(W + i);
        *(float4*)&Ws[r * PITCH + c] = w;
        int gr = rowbase + r;
        float4 xv = (gr < n) ? *(const float4*)(X + (size_t)gr * DNODE + c)
                             : make_float4(0.f, 0.f, 0.f, 0.f);
        *(float4*)&Xs[r * PITCH + c] = xv;
    }
    if (tid < DNODE) bsh[tid] = bias[tid];
    __syncthreads();

    // per-row scale
    if (LOGMAP) {
        int r = tid >> 2, q = tid & 3;
        float s = 0.f;
        #pragma unroll
        for (int c = 0; c < 16; c++) {
            float v = Xs[r * PITCH + q * 16 + c];
            s += v * v;
        }
        s += __shfl_down_sync(0xffffffffu, s, 2, 4);
        s += __shfl_down_sync(0xffffffffu, s, 1, 4);
        if (q == 0) {
            float sc = sqrtf(fabsf(curv[0]));
            float norm = fmaxf(sqrtf(s), EPSN);
            float arg = fminf(sc * norm, ACLIP);
            fac[r] = atanhf(arg) / (sc * norm);
        }
    } else {
        if (tid < DNODE) {
            int gr = rowbase + tid;
            fac[tid] = (gr < n) ? invd[gr] : 0.f;
        }
    }
    __syncthreads();

    // scale X tile in place
    for (int i = tid; i < DNODE * DNODE; i += 256) {
        int r = i >> 6;
        Xs[r * PITCH + (i & 63)] *= fac[r];
    }
    __syncthreads();

    int r4 = tid >> 4;   // 0..15 -> rows r4*4+i
    int c4 = tid & 15;   // 0..15 -> cols c4+16*j
    float acc[4][4] = {};
    #pragma unroll
    for (int k = 0; k < DNODE; k += 4) {
        float4 tv[4], wv[4];
        #pragma unroll
        for (int i = 0; i < 4; i++)
            tv[i] = *(float4*)&Xs[(r4 * 4 + i) * PITCH + k];
        #pragma unroll
        for (int j = 0; j < 4; j++)
            wv[j] = *(float4*)&Ws[(c4 + 16 * j) * PITCH + k];
        #pragma unroll
        for (int i = 0; i < 4; i++)
            #pragma unroll
            for (int j = 0; j < 4; j++) {
                acc[i][j] = fmaf(tv[i].x, wv[j].x, acc[i][j]);
                acc[i][j] = fmaf(tv[i].y, wv[j].y, acc[i][j]);
                acc[i][j] = fmaf(tv[i].z, wv[j].z, acc[i][j]);
                acc[i][j] = fmaf(tv[i].w, wv[j].w, acc[i][j]);
            }
    }
    #pragma unroll
    for (int i = 0; i < 4; i++) {
        int row = rowbase + r4 * 4 + i;
        if (row < n) {
            #pragma unroll
            for (int j = 0; j < 4; j++) {
                int col = c4 + 16 * j;
                out[(size_t)row * DNODE + col] = acc[i][j] + bsh[col];
            }
        }
    }
}

// ============ pull: buf[d] = sum_{e in CSR(d)} h[csr[e]] ============
__global__ __launch_bounds__(256) void pull_k(
    const float* __restrict__ h, const int* __restrict__ rs,
    const int* __restrict__ csr, float* __restrict__ buf, int n)
{
    int gw = (blockIdx.x * 256 + threadIdx.x) >> 5;
    int lane = threadIdx.x & 31;
    if (gw >= n) return;
    int beg = rs[gw], end = rs[gw + 1];
    const float2* hp = (const float2*)h;
    float2 acc = make_float2(0.f, 0.f);
    int i = beg;
    for (; i + 1 < end; i += 2) {
        int s0 = csr[i], s1 = csr[i + 1];
        float2 v0 = hp[(size_t)s0 * 32 + lane];
        float2 v1 = hp[(size_t)s1 * 32 + lane];
        acc.x += v0.x + v1.x;
        acc.y += v0.y + v1.y;
    }
    if (i < end) {
        int s0 = csr[i];
        float2 v0 = hp[(size_t)s0 * 32 + lane];
        acc.x += v0.x;
        acc.y += v0.y;
    }
    ((float2*)buf)[(size_t)gw * 32 + lane] = acc;
}

// ============ out = expmap0(u * invdeg) ============
__global__ __launch_bounds__(256) void expmap_k(
    const float* __restrict__ u, const float* __restrict__ invd,
    const float* __restrict__ curv, float* __restrict__ out, int n)
{
    int gw = (blockIdx.x * 256 + threadIdx.x) >> 5;
    int lane = threadIdx.x & 31;
    if (gw >= n) return;
    float sc = sqrtf(fabsf(curv[0]));
    float w = invd[gw];
    const float2* ur = (const float2*)(u + (size_t)gw * DNODE);
    float2 v = ur[lane];
    float ua = v.x * w, ub = v.y * w;
    float ss = ua * ua + ub * ub;
    #pragma unroll
    for (int o = 16; o; o >>= 1) ss += __shfl_xor_sync(0xffffffffu, ss, o);
    float norm = fmaxf(sqrtf(ss), EPSN);
    float f = tanhf(sc * norm) / (sc * norm);
    float2* orow = (float2*)(out + (size_t)gw * DNODE);
    orow[lane] = make_float2(f * ua, f * ub);
}

// ---------------- launch ----------------
extern "C" void kernel_launch(void* const* d_in, const int* in_sizes, int n_in,
                              void* d_out, int out_size)
{
    const int*   src  = (const int*)d_in[0];
    const int*   dst  = (const int*)d_in[1];
    const float* emb  = (const float*)d_in[2];
    const float* W1   = (const float*)d_in[3];
    const float* b1   = (const float*)d_in[4];
    const float* W2   = (const float*)d_in[5];
    const float* b2   = (const float*)d_in[6];
    const float* curv = (const float*)d_in[7];
    float* out = (float*)d_out;

    const int E = in_sizes[0];
    const int N = in_sizes[2] / DNODE;

    float *h, *buf, *inv;
    int *csr, *rs, *deg, *cur, *incl, *part;
    cudaGetSymbolAddress((void**)&h,    g_h);
    cudaGetSymbolAddress((void**)&buf,  g_buf);
    cudaGetSymbolAddress((void**)&inv,  g_inv);
    cudaGetSymbolAddress((void**)&csr,  g_csr);
    cudaGetSymbolAddress((void**)&rs,   g_rs);
    cudaGetSymbolAddress((void**)&deg,  g_deg);
    cudaGetSymbolAddress((void**)&cur,  g_cur);
    cudaGetSymbolAddress((void**)&incl, g_incl);
    cudaGetSymbolAddress((void**)&part, g_part);

    const int TB = 256;
    int nb_scan = (N + SCAN_BLK - 1) / SCAN_BLK;

    // ---- CSR build (by dst) ----
    zero_int_k<<<(N + TB - 1) / TB, TB>>>(deg, N);
    count_k<<<(E + TB - 1) / TB, TB>>>(dst, deg, E);
    scan1_k<<<nb_scan, TB>>>(deg, incl, part, N);
    scan2_k<<<1, 32>>>(part, nb_scan);
    finalize_k<<<(N + TB - 1) / TB, TB>>>(incl, deg, part, rs, cur, inv, N, E);
    fill_k<<<(E + TB - 1) / TB, TB>>>(src, dst, rs, cur, csr, E);

    int gemm_blocks = (N + DNODE - 1) / DNODE;
    int pull_blocks = (N * 32 + TB - 1) / TB;

    // ---- layer 1: h1 = logmap0(emb) @ W1^T + b1 ; u1 = pull-sum ----
    gemm_k<1><<<gemm_blocks, TB>>>(emb, W1, b1, curv, inv, h, N);
    pull_k<<<pull_blocks, TB>>>(h, rs, csr, buf, N);

    // ---- layer 2: logmap0(expmap0(u)) == u, so t2 = u1*inv_deg directly ----
    gemm_k<0><<<gemm_blocks, TB>>>(buf, W2, b2, curv, inv, h, N);
    pull_k<<<pull_blocks, TB>>>(h, rs, csr, buf, N);

    // ---- out = expmap0(u2 * inv_deg) ----
    expmap_k<<<pull_blocks, TB>>>(buf, inv, curv, out, N);
}